// round 14
// baseline (speedup 1.0000x reference)
#include <cuda_runtime.h>
#include <cuda_bf16.h>
#include <cstdint>
#include <cstdio>

// Problem constants
#define BB   32
#define LLEN 36864
#define CCH  16
#define DDIM 512
#define KW   24
#define LOUT 1536               // LLEN / KW
#define MM   (BB * LOUT)        // 49152 rows
#define KD   384                // CCH * KW reduction dim
#define NOFF 48                 // 2*KW offset channels

// -------- scratch (device globals: allocation-guard safe) --------
__device__ __align__(128) float g_Woff2[KD * NOFF];                  // [kc][o]
__device__ __align__(128) float g_OFF[(size_t)MM * NOFF];            // [m][o]
__device__ __align__(128) __nv_bfloat16 g_Ah[(size_t)MM * KD];       // hi split [m][kc]
__device__ __align__(128) __nv_bfloat16 g_Al[(size_t)MM * KD];       // lo split [m][kc]
__device__ __align__(128) __nv_bfloat16 g_Wh[(size_t)DDIM * KD];     // [d][kc]
__device__ __align__(128) __nv_bfloat16 g_Wl[(size_t)DDIM * KD];     // [d][kc]

// ---------------- helpers ----------------
__device__ __forceinline__ uint32_t smem_u32(const void* p) {
    uint32_t a;
    asm("{ .reg .u64 t; cvta.to.shared.u64 t, %1; cvt.u32.u64 %0, t; }" : "=r"(a) : "l"(p));
    return a;
}
__device__ __forceinline__ void fma2(float2& c, const float2& a, const float2& b) {
    unsigned long long& cu = reinterpret_cast<unsigned long long&>(c);
    const unsigned long long& au = reinterpret_cast<const unsigned long long&>(a);
    const unsigned long long& bu = reinterpret_cast<const unsigned long long&>(b);
    asm("fma.rn.f32x2 %0, %1, %2, %0;" : "+l"(cu) : "l"(au), "l"(bu));
}

#define LDSM_X4(r, addr)                                                         \
    asm volatile("ldmatrix.sync.aligned.m8n8.x4.shared.b16 {%0,%1,%2,%3}, [%4];" \
                 : "=r"((r)[0]), "=r"((r)[1]), "=r"((r)[2]), "=r"((r)[3])        \
                 : "r"(addr))

#define MMA_BF16(c, a, b0, b1)                                                  \
    asm volatile("mma.sync.aligned.m16n8k16.row.col.f32.bf16.bf16.f32 "         \
                 "{%0,%1,%2,%3}, {%4,%5,%6,%7}, {%8,%9}, {%0,%1,%2,%3};"        \
                 : "+f"((c)[0]), "+f"((c)[1]), "+f"((c)[2]), "+f"((c)[3])       \
                 : "r"((a)[0]), "r"((a)[1]), "r"((a)[2]), "r"((a)[3]),          \
                   "r"(b0), "r"(b1))

#define CP_ASYNC16(dst, src) \
    asm volatile("cp.async.cg.shared.global [%0], [%1], 16;" :: "r"(dst), "l"(src))
#define CP_COMMIT() asm volatile("cp.async.commit_group;" ::: "memory")
#define CP_WAIT(n)  asm volatile("cp.async.wait_group %0;" :: "n"(n) : "memory")

// -------- kernel 0: permute weights --------
__global__ void permute_weights_kernel(const float* __restrict__ w_off,
                                       const float* __restrict__ w_def) {
    int t = blockIdx.x * blockDim.x + threadIdx.x;
    if (t < KD * DDIM) {
        int d = t / KD, kc = t % KD;
        int k = kc / CCH, c = kc % CCH;
        float v = w_def[(size_t)d * KD + c * KW + k];
        __nv_bfloat16 h = __float2bfloat16(v);
        __nv_bfloat16 l = __float2bfloat16(v - __bfloat162float(h));
        g_Wh[t] = h;
        g_Wl[t] = l;
    }
    if (t < KD * NOFF) {
        int kc = t / NOFF, o = t % NOFF;
        int k = kc / CCH, c = kc % CCH;
        g_Woff2[t] = w_off[(size_t)o * KD + c * KW + k];
    }
}

// -------- SIMT GEMM for the offset conv (small N=48) --------
template<int BM, int BN, int BK, int TM, int TN>
__global__ void __launch_bounds__((BM / TM) * (BN / TN), 2)
gemm_bias_kernel(const float* __restrict__ A, const float* __restrict__ Bm,
                 const float* __restrict__ bias, float* __restrict__ C,
                 int Kn, int Nn)
{
    constexpr int NT  = (BM / TM) * (BN / TN);
    constexpr int BMp = BM + 4;
    constexpr int NA4 = BM * BK / 4;
    constexpr int NB4 = BK * BN / 4;
    constexpr int LA4 = (NA4 + NT - 1) / NT;
    constexpr int LB4 = (NB4 + NT - 1) / NT;
    static_assert(NA4 % NT == 0, "A tile load must be exact");

    __shared__ __align__(16) float sA[2][BK][BMp];
    __shared__ __align__(16) float sB[2][BK][BN];

    const int tid  = threadIdx.x;
    const int tc   = tid % (BN / TN);
    const int tr   = tid / (BN / TN);
    const int row0 = blockIdx.y * BM;
    const int col0 = blockIdx.x * BN;

    float4 ra[LA4];
    float4 rb[LB4];
    float2 acc[TM][TN / 2];
    #pragma unroll
    for (int i = 0; i < TM; ++i)
        #pragma unroll
        for (int j = 0; j < TN / 2; ++j) acc[i][j] = make_float2(0.f, 0.f);

    auto ldg_stage = [&](int kt) {
        #pragma unroll
        for (int i = 0; i < LA4; ++i) {
            int e4 = tid + i * NT;
            int m  = e4 / (BK / 4);
            int kq = e4 % (BK / 4);
            ra[i] = *(const float4*)&A[(size_t)(row0 + m) * Kn + kt + kq * 4];
        }
        #pragma unroll
        for (int i = 0; i < LB4; ++i) {
            int e4 = tid + i * NT;
            if (NB4 % NT == 0 || e4 < NB4) {
                int kk = e4 / (BN / 4);
                int nq = e4 % (BN / 4);
                rb[i] = *(const float4*)&Bm[(size_t)(kt + kk) * Nn + col0 + nq * 4];
            }
        }
    };
    auto sts_stage = [&](int bf) {
        #pragma unroll
        for (int i = 0; i < LA4; ++i) {
            int e4 = tid + i * NT;
            int m  = e4 / (BK / 4);
            int kq = e4 % (BK / 4);
            sA[bf][kq * 4 + 0][m] = ra[i].x;
            sA[bf][kq * 4 + 1][m] = ra[i].y;
            sA[bf][kq * 4 + 2][m] = ra[i].z;
            sA[bf][kq * 4 + 3][m] = ra[i].w;
        }
        #pragma unroll
        for (int i = 0; i < LB4; ++i) {
            int e4 = tid + i * NT;
            if (NB4 % NT == 0 || e4 < NB4) {
                int kk = e4 / (BN / 4);
                int nq = e4 % (BN / 4);
                *(float4*)&sB[bf][kk][nq * 4] = rb[i];
            }
        }
    };

    ldg_stage(0);
    sts_stage(0);
    __syncthreads();

    const int nkt = Kn / BK;
    for (int t = 0; t < nkt; ++t) {
        const int bf = t & 1;
        if (t + 1 < nkt) ldg_stage((t + 1) * BK);
        #pragma unroll
        for (int kk = 0; kk < BK; ++kk) {
            float af[TM];
            #pragma unroll
            for (int q = 0; q < TM / 4; ++q) {
                float4 v = *(const float4*)&sA[bf][kk][tr * TM + q * 4];
                af[q * 4 + 0] = v.x; af[q * 4 + 1] = v.y;
                af[q * 4 + 2] = v.z; af[q * 4 + 3] = v.w;
            }
            float2 bp[TN / 2];
            #pragma unroll
            for (int j = 0; j < TN / 2; ++j)
                bp[j] = *(const float2*)&sB[bf][kk][tc * TN + 2 * j];
            #pragma unroll
            for (int i = 0; i < TM; ++i) {
                float2 ap; ap.x = af[i]; ap.y = af[i];
                #pragma unroll
                for (int j = 0; j < TN / 2; ++j)
                    fma2(acc[i][j], ap, bp[j]);
            }
        }
        if (t + 1 < nkt) sts_stage(bf ^ 1);
        __syncthreads();
    }

    float bb[TN];
    #pragma unroll
    for (int j = 0; j < TN; ++j) bb[j] = bias[col0 + tc * TN + j];
    #pragma unroll
    for (int i = 0; i < TM; ++i) {
        float* cp = &C[(size_t)(row0 + tr * TM + i) * Nn + col0 + tc * TN];
        #pragma unroll
        for (int j = 0; j < TN / 2; ++j) {
            float2 v = acc[i][j];
            v.x += bb[2 * j];
            v.y += bb[2 * j + 1];
            *(float2*)&cp[2 * j] = v;
        }
    }
}

// -------- sampler: deformable bilinear gather -> bf16 hi/lo split --------
__global__ void sampler_kernel(const float* __restrict__ x) {
    int gtid = blockIdx.x * blockDim.x + threadIdx.x;
    int m    = gtid >> 5;
    int lane = gtid & 31;
    if (m >= MM || lane >= KW) return;
    int b  = m / LOUT;
    int wo = m - b * LOUT;

    float2 d2 = ((const float2*)(g_OFF + (size_t)m * NOFF))[lane]; // (dy, dx)
    float dy = d2.x, dx = d2.y;

    float wy = fmaxf(0.f, 1.f - fabsf(dy));
    float px = (float)(wo * KW + lane) + dx;
    bool valid = (px > -1.f) && (px < (float)LLEN);
    float x0f = floorf(px);
    float lw  = px - x0f;
    int i0 = (int)x0f;
    int i1 = i0 + 1;
    float w0 = (valid && i0 >= 0 && i0 < LLEN) ? (1.f - lw) * wy : 0.f;
    float w1 = (valid && i1 >= 0 && i1 < LLEN) ? lw * wy : 0.f;
    int i0c = min(max(i0, 0), LLEN - 1);
    int i1c = min(max(i1, 0), LLEN - 1);

    const float4* p0 = (const float4*)(x + ((size_t)b * LLEN + i0c) * CCH);
    const float4* p1 = (const float4*)(x + ((size_t)b * LLEN + i1c) * CCH);

    uint32_t wh[8], wl[8];
    #pragma unroll
    for (int q = 0; q < 4; ++q) {
        float4 v0 = p0[q], v1 = p1[q];
        float r0 = w0 * v0.x + w1 * v1.x;
        float r1 = w0 * v0.y + w1 * v1.y;
        float r2 = w0 * v0.z + w1 * v1.z;
        float r3 = w0 * v0.w + w1 * v1.w;
        __nv_bfloat16 h0 = __float2bfloat16(r0), h1 = __float2bfloat16(r1);
        __nv_bfloat16 h2 = __float2bfloat16(r2), h3 = __float2bfloat16(r3);
        __nv_bfloat16 l0 = __float2bfloat16(r0 - __bfloat162float(h0));
        __nv_bfloat16 l1 = __float2bfloat16(r1 - __bfloat162float(h1));
        __nv_bfloat16 l2 = __float2bfloat16(r2 - __bfloat162float(h2));
        __nv_bfloat16 l3 = __float2bfloat16(r3 - __bfloat162float(h3));
        wh[q * 2 + 0] = (uint32_t)__bfloat16_as_ushort(h0) | ((uint32_t)__bfloat16_as_ushort(h1) << 16);
        wh[q * 2 + 1] = (uint32_t)__bfloat16_as_ushort(h2) | ((uint32_t)__bfloat16_as_ushort(h3) << 16);
        wl[q * 2 + 0] = (uint32_t)__bfloat16_as_ushort(l0) | ((uint32_t)__bfloat16_as_ushort(l1) << 16);
        wl[q * 2 + 1] = (uint32_t)__bfloat16_as_ushort(l2) | ((uint32_t)__bfloat16_as_ushort(l3) << 16);
    }
    uint4* ph = (uint4*)(g_Ah + (size_t)m * KD + lane * CCH);
    uint4* pl = (uint4*)(g_Al + (size_t)m * KD + lane * CCH);
    ph[0] = make_uint4(wh[0], wh[1], wh[2], wh[3]);
    ph[1] = make_uint4(wh[4], wh[5], wh[6], wh[7]);
    pl[0] = make_uint4(wl[0], wl[1], wl[2], wl[3]);
    pl[1] = make_uint4(wl[4], wl[5], wl[6], wl[7]);
}

// -------- main projection: mma.sync bf16-split tensor-core GEMM --------
// CTA tile 128x64, BK=32, 4-stage cp.async pipeline (wait<=2), 96KB smem -> 2 CTAs/SM.
// 8 warps: warp_m = wid&3 (32 rows), warp_n = wid>>2 (32 cols).
// Per k16-step: 3 split products Ah*Wh + Ah*Wl + Al*Wh, fp32 accumulate.
#define G2_BN      64
#define G2_BK      32
#define G2_NCH     (KD / G2_BK)             // 12
#define G2_STAGES  4
#define G2_AT_B    (128 * G2_BK * 2)        // 8192 B per A tile
#define G2_WT_B    (G2_BN * G2_BK * 2)      // 4096 B per W tile
#define G2_STAGE_B (2 * G2_AT_B + 2 * G2_WT_B)  // 24576 B
#define G2_SMEM    (G2_STAGES * G2_STAGE_B)     // 98304 B

// swizzled byte offset inside a [rows][32] bf16 tile (rows of 64B = 4 x 16B chunks)
__device__ __forceinline__ uint32_t g2_swz(int row, int chunk) {
    return (uint32_t)(row * 64 + ((chunk ^ ((row >> 1) & 3)) << 4));
}

__global__ void __launch_bounds__(256, 2)
gemm2_mma(const __nv_bfloat16* __restrict__ Ah, const __nv_bfloat16* __restrict__ Al,
          const __nv_bfloat16* __restrict__ Wh, const __nv_bfloat16* __restrict__ Wl,
          const float* __restrict__ bias, float* __restrict__ out)
{
    extern __shared__ __align__(1024) char smem[];
    const uint32_t sbase = smem_u32(smem);

    const int tid    = threadIdx.x;
    const int wid    = tid >> 5;
    const int lane   = tid & 31;
    const int warp_m = wid & 3;
    const int warp_n = wid >> 2;
    const int row0   = blockIdx.y * 128;
    const int col0   = blockIdx.x * G2_BN;

    const __nv_bfloat16* asrc[2] = { Ah + (size_t)row0 * KD, Al + (size_t)row0 * KD };
    const __nv_bfloat16* wsrc[2] = { Wh + (size_t)col0 * KD, Wl + (size_t)col0 * KD };

    auto load_stage = [&](int t) {
        const int kt = t * G2_BK;
        const uint32_t sb = sbase + (t % G2_STAGES) * G2_STAGE_B;
        // A tiles: 2 x 512 16B-chunks = ids [0, 1024)
        #pragma unroll
        for (int i = 0; i < 4; ++i) {
            int id  = i * 256 + tid;
            int mat = id >> 9;
            int j   = id & 511;
            int row = j >> 2;
            int c   = j & 3;
            const __nv_bfloat16* src = asrc[mat] + (size_t)row * KD + kt + c * 8;
            CP_ASYNC16(sb + mat * G2_AT_B + g2_swz(row, c), src);
        }
        // W tiles: 2 x 256 16B-chunks = ids [0, 512)
        {
            int id  = tid;           // 256 threads cover mat 0
            int row = (id & 255) >> 2;
            int c   = id & 3;
            int mat = id >> 8;       // 0 for tid<256 ... need two passes
            (void)mat;
            const __nv_bfloat16* src0 = wsrc[0] + (size_t)row * KD + kt + c * 8;
            CP_ASYNC16(sb + 2 * G2_AT_B + g2_swz(row, c), src0);
            const __nv_bfloat16* src1 = wsrc[1] + (size_t)row * KD + kt + c * 8;
            CP_ASYNC16(sb + 2 * G2_AT_B + G2_WT_B + g2_swz(row, c), src1);
        }
    };

    float acc[2][4][4];
    #pragma unroll
    for (int mf = 0; mf < 2; ++mf)
        #pragma unroll
        for (int nf = 0; nf < 4; ++nf)
            #pragma unroll
            for (int q = 0; q < 4; ++q) acc[mf][nf][q] = 0.f;

    // ldmatrix lane-address components
    const int a_row = warp_m * 32 + (lane & 15);                     // + mf*16
    const int a_chb = (lane >> 4);                                   // + 2*ks
    const int b_row = warp_n * 32 + (lane & 7) + ((lane >> 4) << 3); // + nf4*16
    const int b_chb = ((lane >> 3) & 1);                             // + 2*ks

    load_stage(0); CP_COMMIT();
    load_stage(1); CP_COMMIT();
    load_stage(2); CP_COMMIT();

    #pragma unroll 1
    for (int t = 0; t < G2_NCH; ++t) {
        CP_WAIT(2);                 // stage t resident (t+1, t+2 may be pending)
        __syncthreads();            // all reads of stage t-1 done -> slot (t+3)%4 reusable
        if (t + 3 < G2_NCH) load_stage(t + 3);
        CP_COMMIT();                // uniform group count at the tail

        const uint32_t sb = sbase + (t % G2_STAGES) * G2_STAGE_B;
        #pragma unroll
        for (int ks = 0; ks < 2; ++ks) {
            uint32_t afh[2][4], afl[2][4];
            #pragma unroll
            for (int mf = 0; mf < 2; ++mf) {
                uint32_t o = g2_swz(a_row + mf * 16, 2 * ks + a_chb);
                LDSM_X4(afh[mf], sb + 0 * G2_AT_B + o);
                LDSM_X4(afl[mf], sb + 1 * G2_AT_B + o);
            }
            // Wh pass: mma with both Ah and Al
            #pragma unroll
            for (int nf4 = 0; nf4 < 2; ++nf4) {
                uint32_t bfr[4];
                LDSM_X4(bfr, sb + 2 * G2_AT_B + g2_swz(b_row + nf4 * 16, 2 * ks + b_chb));
                #pragma unroll
                for (int p = 0; p < 2; ++p) {
                    const int nf = 2 * nf4 + p;
                    #pragma unroll
                    for (int mf = 0; mf < 2; ++mf) {
                        MMA_BF16(acc[mf][nf], afh[mf], bfr[2 * p], bfr[2 * p + 1]);
                        MMA_BF16(acc[mf][nf], afl[mf], bfr[2 * p], bfr[2 * p + 1]);
                    }
                }
            }
            // Wl pass: mma with Ah only
            #pragma unroll
            for (int nf4 = 0; nf4 < 2; ++nf4) {
                uint32_t bfr[4];
                LDSM_X4(bfr, sb + 2 * G2_AT_B + G2_WT_B + g2_swz(b_row + nf4 * 16, 2 * ks + b_chb));
                #pragma unroll
                for (int p = 0; p < 2; ++p) {
                    const int nf = 2 * nf4 + p;
                    #pragma unroll
                    for (int mf = 0; mf < 2; ++mf)
                        MMA_BF16(acc[mf][nf], afh[mf], bfr[2 * p], bfr[2 * p + 1]);
                }
            }
        }
    }

    // epilogue: fragment -> gmem with bias
    #pragma unroll
    for (int mf = 0; mf < 2; ++mf) {
        const int r = row0 + warp_m * 32 + mf * 16 + (lane >> 2);
        #pragma unroll
        for (int nf = 0; nf < 4; ++nf) {
            const int n = col0 + warp_n * 32 + nf * 8 + (lane & 3) * 2;
            float2 b2 = *(const float2*)&bias[n];
            float2 v0, v1;
            v0.x = acc[mf][nf][0] + b2.x;
            v0.y = acc[mf][nf][1] + b2.y;
            v1.x = acc[mf][nf][2] + b2.x;
            v1.y = acc[mf][nf][3] + b2.y;
            *(float2*)&out[(size_t)r * DDIM + n]       = v0;
            *(float2*)&out[(size_t)(r + 8) * DDIM + n] = v1;
        }
    }
}

extern "C" void kernel_launch(void* const* d_in, const int* in_sizes, int n_in,
                              void* d_out, int out_size) {
    (void)in_sizes; (void)n_in; (void)out_size;
    const float* x     = (const float*)d_in[0];
    const float* w_off = (const float*)d_in[1];
    const float* b_off = (const float*)d_in[2];
    const float* w_def = (const float*)d_in[3];
    const float* b_def = (const float*)d_in[4];
    float* out = (float*)d_out;

    void* p;
    cudaGetSymbolAddress(&p, g_Woff2); float* woff2 = (float*)p;
    cudaGetSymbolAddress(&p, g_OFF);   float* off   = (float*)p;
    cudaGetSymbolAddress(&p, g_Ah);    __nv_bfloat16* ah = (__nv_bfloat16*)p;
    cudaGetSymbolAddress(&p, g_Al);    __nv_bfloat16* al = (__nv_bfloat16*)p;
    cudaGetSymbolAddress(&p, g_Wh);    __nv_bfloat16* wh = (__nv_bfloat16*)p;
    cudaGetSymbolAddress(&p, g_Wl);    __nv_bfloat16* wl = (__nv_bfloat16*)p;

    cudaFuncSetAttribute(gemm2_mma, cudaFuncAttributeMaxDynamicSharedMemorySize, G2_SMEM);

    // 0) permute/split weights
    permute_weights_kernel<<<(KD * DDIM + 255) / 256, 256>>>(w_off, w_def);

    // 1) offset conv: x (viewed [M,384]) @ Woff2[384,48] + b_off -> g_OFF
    gemm_bias_kernel<64, 48, 16, 4, 6><<<dim3(1, MM / 64), 128>>>(
        x, woff2, b_off, off, KD, NOFF);

    // 2) deformable bilinear sampling -> bf16 hi/lo [M,384]
    sampler_kernel<<<MM / 8, 256>>>(x);

    // 3) main projection on tensor cores: (Ah+Al) @ (Wh+Wl)^T + b_def -> out
    gemm2_mma<<<dim3(DDIM / G2_BN, MM / 128), 256, G2_SMEM>>>(ah, al, wh, wl, b_def, out);
}

// round 15
// speedup vs baseline: 1.1400x; 1.1400x over previous
#include <cuda_runtime.h>
#include <cuda_bf16.h>
#include <cstdint>
#include <cstdio>

// Problem constants
#define BB   32
#define LLEN 36864
#define CCH  16
#define DDIM 512
#define KW   24
#define LOUT 1536               // LLEN / KW
#define MM   (BB * LOUT)        // 49152 rows
#define KD   384                // CCH * KW reduction dim
#define NOFF 48                 // 2*KW offset channels

// -------- scratch (device globals: allocation-guard safe) --------
__device__ __align__(128) __nv_bfloat16 g_WoffH[NOFF * KD];          // [o][kc] hi
__device__ __align__(128) __nv_bfloat16 g_WoffL[NOFF * KD];          // [o][kc] lo
__device__ __align__(128) float g_OFF[(size_t)MM * NOFF];            // [m][o]
__device__ __align__(128) __nv_bfloat16 g_Ah[(size_t)MM * KD];       // hi split [m][kc]
__device__ __align__(128) __nv_bfloat16 g_Al[(size_t)MM * KD];       // lo split [m][kc]
__device__ __align__(128) __nv_bfloat16 g_Wh[(size_t)DDIM * KD];     // [d][kc]
__device__ __align__(128) __nv_bfloat16 g_Wl[(size_t)DDIM * KD];     // [d][kc]

// ---------------- helpers ----------------
__device__ __forceinline__ uint32_t smem_u32(const void* p) {
    uint32_t a;
    asm("{ .reg .u64 t; cvta.to.shared.u64 t, %1; cvt.u32.u64 %0, t; }" : "=r"(a) : "l"(p));
    return a;
}

#define LDSM_X4(r, addr)                                                         \
    asm volatile("ldmatrix.sync.aligned.m8n8.x4.shared.b16 {%0,%1,%2,%3}, [%4];" \
                 : "=r"((r)[0]), "=r"((r)[1]), "=r"((r)[2]), "=r"((r)[3])        \
                 : "r"(addr))

#define MMA_BF16(c, a, b0, b1)                                                  \
    asm volatile("mma.sync.aligned.m16n8k16.row.col.f32.bf16.bf16.f32 "         \
                 "{%0,%1,%2,%3}, {%4,%5,%6,%7}, {%8,%9}, {%0,%1,%2,%3};"        \
                 : "+f"((c)[0]), "+f"((c)[1]), "+f"((c)[2]), "+f"((c)[3])       \
                 : "r"((a)[0]), "r"((a)[1]), "r"((a)[2]), "r"((a)[3]),          \
                   "r"(b0), "r"(b1))

#define CP_ASYNC16(dst, src) \
    asm volatile("cp.async.cg.shared.global [%0], [%1], 16;" :: "r"(dst), "l"(src))
#define CP_COMMIT() asm volatile("cp.async.commit_group;" ::: "memory")
#define CP_WAIT(n)  asm volatile("cp.async.wait_group %0;" :: "n"(n) : "memory")

#define STS_V4(addr, a, b, c, d)                                   \
    asm volatile("st.shared.v4.b32 [%0], {%1, %2, %3, %4};"        \
                 :: "r"(addr), "r"(a), "r"(b), "r"(c), "r"(d) : "memory")

// swizzled byte offset inside a [rows][32] bf16 tile (rows of 64B = 4 x 16B chunks)
__device__ __forceinline__ uint32_t g2_swz(int row, int chunk) {
    return (uint32_t)(row * 64 + ((chunk ^ ((row >> 1) & 3)) << 4));
}

__device__ __forceinline__ uint32_t pack_hi2(float a, float b, uint32_t& lo) {
    __nv_bfloat16 h0 = __float2bfloat16(a), h1 = __float2bfloat16(b);
    __nv_bfloat16 l0 = __float2bfloat16(a - __bfloat162float(h0));
    __nv_bfloat16 l1 = __float2bfloat16(b - __bfloat162float(h1));
    lo = (uint32_t)__bfloat16_as_ushort(l0) | ((uint32_t)__bfloat16_as_ushort(l1) << 16);
    return (uint32_t)__bfloat16_as_ushort(h0) | ((uint32_t)__bfloat16_as_ushort(h1) << 16);
}

// -------- kernel 0: permute + split weights --------
// kc = k*16 + c matches x's natural flat layout.
__global__ void permute_weights_kernel(const float* __restrict__ w_off,
                                       const float* __restrict__ w_def) {
    int t = blockIdx.x * blockDim.x + threadIdx.x;
    if (t < KD * DDIM) {
        int d = t / KD, kc = t % KD;
        int k = kc >> 4, c = kc & 15;
        float v = w_def[(size_t)d * KD + c * KW + k];
        __nv_bfloat16 h = __float2bfloat16(v);
        __nv_bfloat16 l = __float2bfloat16(v - __bfloat162float(h));
        g_Wh[t] = h;
        g_Wl[t] = l;
    }
    if (t < NOFF * KD) {
        int o = t / KD, kc = t % KD;
        int k = kc >> 4, c = kc & 15;
        float v = w_off[(size_t)o * KD + c * KW + k];
        __nv_bfloat16 h = __float2bfloat16(v);
        __nv_bfloat16 l = __float2bfloat16(v - __bfloat162float(h));
        g_WoffH[t] = h;
        g_WoffL[t] = l;
    }
}

// -------- offset conv on tensor cores: x[M,384] @ WoffT[384,48] + b_off -> g_OFF --------
// CTA tile 128 x 48, 8 warps (warp = 16 rows, full N=48). A converted fp32->bf16 split
// in registers (LDG->cvt->STS), W via cp.async. 3 stages, one sync per K-chunk.
#define OC_BK      32
#define OC_NCH     (KD / OC_BK)                 // 12
#define OC_AT_B    (128 * OC_BK * 2)            // 8192 per A split tile
#define OC_WT_B    (NOFF * OC_BK * 2)           // 3072 per W split tile
#define OC_STAGE_B (2 * OC_AT_B + 2 * OC_WT_B)  // 22528
#define OC_SMEM    (3 * OC_STAGE_B)             // 67584

__global__ void __launch_bounds__(256, 2)
offconv_mma(const float* __restrict__ x, const float* __restrict__ b_off,
            float* __restrict__ offout)
{
    extern __shared__ __align__(1024) char smem[];
    const uint32_t sbase = smem_u32(smem);

    const int tid  = threadIdx.x;
    const int wid  = tid >> 5;
    const int lane = tid & 31;
    const int row0 = blockIdx.x * 128;

    // producer A task: row = tid>>1, kc-half = (tid&1)*16
    const int p_row  = tid >> 1;
    const int p_half = tid & 1;
    const float* xrow = x + (size_t)(row0 + p_row) * KD + p_half * 16;

    uint32_t vh[8], vl[8];
    auto gather_a = [&](int t) {
        const float4* src = (const float4*)(xrow + t * OC_BK);
        #pragma unroll
        for (int q = 0; q < 4; ++q) {
            float4 v = src[q];
            vh[q * 2 + 0] = pack_hi2(v.x, v.y, vl[q * 2 + 0]);
            vh[q * 2 + 1] = pack_hi2(v.z, v.w, vl[q * 2 + 1]);
        }
    };
    auto sts_a = [&](int t) {
        const uint32_t sb = sbase + (t % 3) * OC_STAGE_B;
        const uint32_t o0 = g2_swz(p_row, p_half * 2);
        const uint32_t o1 = g2_swz(p_row, p_half * 2 + 1);
        STS_V4(sb + o0, vh[0], vh[1], vh[2], vh[3]);
        STS_V4(sb + o1, vh[4], vh[5], vh[6], vh[7]);
        STS_V4(sb + OC_AT_B + o0, vl[0], vl[1], vl[2], vl[3]);
        STS_V4(sb + OC_AT_B + o1, vl[4], vl[5], vl[6], vl[7]);
    };
    auto cpw = [&](int t) {
        const int kt = t * OC_BK;
        const uint32_t sb = sbase + (t % 3) * OC_STAGE_B + 2 * OC_AT_B;
        #pragma unroll
        for (int i = 0; i < 2; ++i) {
            int id = i * 256 + tid;
            if (id < 2 * (OC_WT_B / 16)) {           // 384 chunks total
                int sp  = id / (OC_WT_B / 16);       // split 0=hi, 1=lo
                int j   = id % (OC_WT_B / 16);
                int row = j >> 2;
                int c   = j & 3;
                const __nv_bfloat16* src =
                    (sp ? g_WoffL : g_WoffH) + (size_t)row * KD + kt + c * 8;
                CP_ASYNC16(sb + sp * OC_WT_B + g2_swz(row, c), src);
            }
        }
    };

    float acc[6][4];
    #pragma unroll
    for (int nf = 0; nf < 6; ++nf)
        #pragma unroll
        for (int q = 0; q < 4; ++q) acc[nf][q] = 0.f;

    const int a_row = wid * 16 + (lane & 15);
    const int a_chb = lane >> 4;
    const int b_row = (lane & 7) + ((lane >> 4) << 3);
    const int b_chb = (lane >> 3) & 1;

    gather_a(0); sts_a(0); cpw(0); CP_COMMIT();
    gather_a(1); sts_a(1); cpw(1); CP_COMMIT();
    gather_a(2);

    #pragma unroll 1
    for (int t = 0; t < OC_NCH; ++t) {
        CP_WAIT(1);
        __syncthreads();            // stage t ready; stage (t-1)%3 free
        if (t + 2 < OC_NCH) { sts_a(t + 2); cpw(t + 2); }
        CP_COMMIT();

        const uint32_t sb = sbase + (t % 3) * OC_STAGE_B;
        #pragma unroll
        for (int ks = 0; ks < 2; ++ks) {
            uint32_t afh[4], afl[4];
            uint32_t oa = g2_swz(a_row, 2 * ks + a_chb);
            LDSM_X4(afh, sb + oa);
            LDSM_X4(afl, sb + OC_AT_B + oa);
            #pragma unroll
            for (int nf4 = 0; nf4 < 3; ++nf4) {
                uint32_t bfr[4];
                LDSM_X4(bfr, sb + 2 * OC_AT_B + g2_swz(b_row + nf4 * 16, 2 * ks + b_chb));
                #pragma unroll
                for (int p = 0; p < 2; ++p) {
                    const int nf = 2 * nf4 + p;
                    MMA_BF16(acc[nf], afh, bfr[2 * p], bfr[2 * p + 1]);
                    MMA_BF16(acc[nf], afl, bfr[2 * p], bfr[2 * p + 1]);
                }
            }
            #pragma unroll
            for (int nf4 = 0; nf4 < 3; ++nf4) {
                uint32_t bfr[4];
                LDSM_X4(bfr, sb + 2 * OC_AT_B + OC_WT_B + g2_swz(b_row + nf4 * 16, 2 * ks + b_chb));
                #pragma unroll
                for (int p = 0; p < 2; ++p) {
                    const int nf = 2 * nf4 + p;
                    MMA_BF16(acc[nf], afh, bfr[2 * p], bfr[2 * p + 1]);
                }
            }
        }
        if (t + 3 < OC_NCH) gather_a(t + 3);
    }

    // epilogue with bias
    const int r = row0 + wid * 16 + (lane >> 2);
    #pragma unroll
    for (int nf = 0; nf < 6; ++nf) {
        const int o = nf * 8 + (lane & 3) * 2;
        float2 b2 = *(const float2*)&b_off[o];
        float2 v0, v1;
        v0.x = acc[nf][0] + b2.x;
        v0.y = acc[nf][1] + b2.y;
        v1.x = acc[nf][2] + b2.x;
        v1.y = acc[nf][3] + b2.y;
        *(float2*)&offout[(size_t)r * NOFF + o]       = v0;
        *(float2*)&offout[(size_t)(r + 8) * NOFF + o] = v1;
    }
}

// -------- sampler: deformable bilinear gather -> bf16 hi/lo split --------
__global__ void sampler_kernel(const float* __restrict__ x) {
    int gtid = blockIdx.x * blockDim.x + threadIdx.x;
    int m    = gtid >> 5;
    int lane = gtid & 31;
    if (m >= MM || lane >= KW) return;
    int b  = m / LOUT;
    int wo = m - b * LOUT;

    float2 d2 = ((const float2*)(g_OFF + (size_t)m * NOFF))[lane]; // (dy, dx)
    float dy = d2.x, dx = d2.y;

    float wy = fmaxf(0.f, 1.f - fabsf(dy));
    float px = (float)(wo * KW + lane) + dx;
    bool valid = (px > -1.f) && (px < (float)LLEN);
    float x0f = floorf(px);
    float lw  = px - x0f;
    int i0 = (int)x0f;
    int i1 = i0 + 1;
    float w0 = (valid && i0 >= 0 && i0 < LLEN) ? (1.f - lw) * wy : 0.f;
    float w1 = (valid && i1 >= 0 && i1 < LLEN) ? lw * wy : 0.f;
    int i0c = min(max(i0, 0), LLEN - 1);
    int i1c = min(max(i1, 0), LLEN - 1);

    const float4* p0 = (const float4*)(x + ((size_t)b * LLEN + i0c) * CCH);
    const float4* p1 = (const float4*)(x + ((size_t)b * LLEN + i1c) * CCH);

    uint32_t wh[8], wl[8];
    #pragma unroll
    for (int q = 0; q < 4; ++q) {
        float4 v0 = p0[q], v1 = p1[q];
        float r0 = w0 * v0.x + w1 * v1.x;
        float r1 = w0 * v0.y + w1 * v1.y;
        float r2 = w0 * v0.z + w1 * v1.z;
        float r3 = w0 * v0.w + w1 * v1.w;
        wh[q * 2 + 0] = pack_hi2(r0, r1, wl[q * 2 + 0]);
        wh[q * 2 + 1] = pack_hi2(r2, r3, wl[q * 2 + 1]);
    }
    uint4* ph = (uint4*)(g_Ah + (size_t)m * KD + lane * CCH);
    uint4* pl = (uint4*)(g_Al + (size_t)m * KD + lane * CCH);
    ph[0] = make_uint4(wh[0], wh[1], wh[2], wh[3]);
    ph[1] = make_uint4(wh[4], wh[5], wh[6], wh[7]);
    pl[0] = make_uint4(wl[0], wl[1], wl[2], wl[3]);
    pl[1] = make_uint4(wl[4], wl[5], wl[6], wl[7]);
}

// -------- main projection: mma.sync bf16-split tensor-core GEMM (R13 config) --------
// CTA tile 128x128, BK=32 bf16, 3-stage cp.async pipeline, 96KB smem -> 2 CTAs/SM.
#define G2_BK      32
#define G2_NCH     (KD / G2_BK)             // 12
#define G2_STAGES  3
#define G2_TILE_B  (128 * G2_BK * 2)        // 8192 B per matrix tile
#define G2_STAGE_B (4 * G2_TILE_B)          // 32768 B (Ah, Al, Wh, Wl)
#define G2_SMEM    (G2_STAGES * G2_STAGE_B) // 98304 B

__global__ void __launch_bounds__(256, 2)
gemm2_mma(const __nv_bfloat16* __restrict__ Ah, const __nv_bfloat16* __restrict__ Al,
          const __nv_bfloat16* __restrict__ Wh, const __nv_bfloat16* __restrict__ Wl,
          const float* __restrict__ bias, float* __restrict__ out)
{
    extern __shared__ __align__(1024) char smem[];
    const uint32_t sbase = smem_u32(smem);

    const int tid    = threadIdx.x;
    const int wid    = tid >> 5;
    const int lane   = tid & 31;
    const int warp_m = wid & 3;
    const int warp_n = wid >> 2;
    const int row0   = blockIdx.y * 128;
    const int col0   = blockIdx.x * 128;

    const __nv_bfloat16* srcs[4] = {
        Ah + (size_t)row0 * KD, Al + (size_t)row0 * KD,
        Wh + (size_t)col0 * KD, Wl + (size_t)col0 * KD };

    auto load_stage = [&](int t) {
        const int kt = t * G2_BK;
        const uint32_t sb = sbase + (t % G2_STAGES) * G2_STAGE_B;
        #pragma unroll
        for (int i = 0; i < 8; ++i) {
            int id  = i * 256 + tid;
            int mat = id >> 9;            // 512 chunks per tile
            int j   = id & 511;
            int row = j >> 2;
            int c   = j & 3;
            const __nv_bfloat16* src = srcs[mat] + (size_t)row * KD + kt + c * 8;
            CP_ASYNC16(sb + mat * G2_TILE_B + g2_swz(row, c), src);
        }
    };

    float acc[2][8][4];
    #pragma unroll
    for (int mf = 0; mf < 2; ++mf)
        #pragma unroll
        for (int nf = 0; nf < 8; ++nf)
            #pragma unroll
            for (int q = 0; q < 4; ++q) acc[mf][nf][q] = 0.f;

    const int a_row = warp_m * 32 + (lane & 15);     // + mf*16
    const int a_chb = (lane >> 4);                   // + 2*ks
    const int b_row = warp_n * 64 + (lane & 7) + ((lane >> 4) << 3);  // + nf4*16
    const int b_chb = ((lane >> 3) & 1);             // + 2*ks

    load_stage(0); CP_COMMIT();
    load_stage(1); CP_COMMIT();

    #pragma unroll 1
    for (int t = 0; t < G2_NCH; ++t) {
        CP_WAIT(1);                 // stage t resident (only t+1 may be pending)
        __syncthreads();            // all reads of stage (t-1) are done
        if (t + 2 < G2_NCH) load_stage(t + 2);
        CP_COMMIT();

        const uint32_t sb = sbase + (t % G2_STAGES) * G2_STAGE_B;
        #pragma unroll
        for (int ks = 0; ks < 2; ++ks) {
            uint32_t afh[2][4], afl[2][4];
            #pragma unroll
            for (int mf = 0; mf < 2; ++mf) {
                uint32_t o = g2_swz(a_row + mf * 16, 2 * ks + a_chb);
                LDSM_X4(afh[mf], sb + 0 * G2_TILE_B + o);
                LDSM_X4(afl[mf], sb + 1 * G2_TILE_B + o);
            }
            #pragma unroll
            for (int nf4 = 0; nf4 < 4; ++nf4) {
                uint32_t bfr[4];
                LDSM_X4(bfr, sb + 2 * G2_TILE_B + g2_swz(b_row + nf4 * 16, 2 * ks + b_chb));
                #pragma unroll
                for (int p = 0; p < 2; ++p) {
                    const int nf = 2 * nf4 + p;
                    #pragma unroll
                    for (int mf = 0; mf < 2; ++mf) {
                        MMA_BF16(acc[mf][nf], afh[mf], bfr[2 * p], bfr[2 * p + 1]);
                        MMA_BF16(acc[mf][nf], afl[mf], bfr[2 * p], bfr[2 * p + 1]);
                    }
                }
            }
            #pragma unroll
            for (int nf4 = 0; nf4 < 4; ++nf4) {
                uint32_t bfr[4];
                LDSM_X4(bfr, sb + 3 * G2_TILE_B + g2_swz(b_row + nf4 * 16, 2 * ks + b_chb));
                #pragma unroll
                for (int p = 0; p < 2; ++p) {
                    const int nf = 2 * nf4 + p;
                    #pragma unroll
                    for (int mf = 0; mf < 2; ++mf)
                        MMA_BF16(acc[mf][nf], afh[mf], bfr[2 * p], bfr[2 * p + 1]);
                }
            }
        }
    }

    #pragma unroll
    for (int mf = 0; mf < 2; ++mf) {
        const int r = row0 + warp_m * 32 + mf * 16 + (lane >> 2);
        #pragma unroll
        for (int nf = 0; nf < 8; ++nf) {
            const int n = col0 + warp_n * 64 + nf * 8 + (lane & 3) * 2;
            float2 b2 = *(const float2*)&bias[n];
            float2 v0, v1;
            v0.x = acc[mf][nf][0] + b2.x;
            v0.y = acc[mf][nf][1] + b2.y;
            v1.x = acc[mf][nf][2] + b2.x;
            v1.y = acc[mf][nf][3] + b2.y;
            *(float2*)&out[(size_t)r * DDIM + n]       = v0;
            *(float2*)&out[(size_t)(r + 8) * DDIM + n] = v1;
        }
    }
}

extern "C" void kernel_launch(void* const* d_in, const int* in_sizes, int n_in,
                              void* d_out, int out_size) {
    (void)in_sizes; (void)n_in; (void)out_size;
    const float* x     = (const float*)d_in[0];
    const float* w_off = (const float*)d_in[1];
    const float* b_off = (const float*)d_in[2];
    const float* w_def = (const float*)d_in[3];
    const float* b_def = (const float*)d_in[4];
    float* out = (float*)d_out;

    void* p;
    cudaGetSymbolAddress(&p, g_OFF);   float* off   = (float*)p;
    cudaGetSymbolAddress(&p, g_Ah);    __nv_bfloat16* ah = (__nv_bfloat16*)p;
    cudaGetSymbolAddress(&p, g_Al);    __nv_bfloat16* al = (__nv_bfloat16*)p;
    cudaGetSymbolAddress(&p, g_Wh);    __nv_bfloat16* wh = (__nv_bfloat16*)p;
    cudaGetSymbolAddress(&p, g_Wl);    __nv_bfloat16* wl = (__nv_bfloat16*)p;

    cudaFuncSetAttribute(gemm2_mma, cudaFuncAttributeMaxDynamicSharedMemorySize, G2_SMEM);
    cudaFuncSetAttribute(offconv_mma, cudaFuncAttributeMaxDynamicSharedMemorySize, OC_SMEM);

    // 0) permute/split weights (both W_def and W_off)
    permute_weights_kernel<<<(KD * DDIM + 255) / 256, 256>>>(w_off, w_def);

    // 1) offset conv on tensor cores: x [M,384] @ WoffT [384,48] + b_off -> g_OFF
    offconv_mma<<<MM / 128, 256, OC_SMEM>>>(x, b_off, off);

    // 2) deformable bilinear sampling -> bf16 hi/lo [M,384]
    sampler_kernel<<<MM / 8, 256>>>(x);

    // 3) main projection on tensor cores: (Ah+Al) @ (Wh+Wl)^T + b_def -> out
    gemm2_mma<<<dim3(DDIM / 128, MM / 128), 256, G2_SMEM>>>(ah, al, wh, wl, b_def, out);
}